// round 10
// baseline (speedup 1.0000x reference)
#include <cuda_runtime.h>
#include <cuda_fp16.h>
#include <cstdint>

#define BN    128
#define NN    12000
#define NOMIC 3600
#define NFN   7000
#define FCC   56000
#define EE    57000
#define LL    4
#define LAT   100
#define EPSV  1e-5f

// ---------------- scratch (device globals; no allocation allowed) ----------------
__device__ float  g_xT[NN * BN];          // x transposed [n][b]
__device__ float  g_xe0[EE * BN];         // edge state ping
__device__ float  g_xe1[EE * BN];         // edge state pong
__device__ __half g_zh[FCC * BN];         // z (pre-sigmoid) fp16
__device__ __half g_s [FCC * BN];         // s = sigmoid(LN(z))  fp16
__device__ float  g_b3cum[LL * EE];       // cumulative b3 sums
__device__ float  g_hraw[LAT * BN];       // gemm1 accumulator [j][b]
__device__ float  g_hT  [LAT * BN];       // elu(h) transposed [k][b]
__device__ float  g_red [2 * BN];         // LN sum/sumsq (raw)
__device__ int    g_fcount[NFN];          // out-edges per source function
__device__ int2   g_fbucket[NFN * 64];    // (p, e) bucket entries
__device__ unsigned char g_etouch[EE];    // edge is a scatter destination

// ---------------- helpers ----------------
__device__ __forceinline__ float4 ld_half4(const __half* p) {
    union { uint2 u; __half2 h[2]; } v;
    v.u = *reinterpret_cast<const uint2*>(p);
    float2 a = __half22float2(v.h[0]);
    float2 b = __half22float2(v.h[1]);
    return make_float4(a.x, a.y, b.x, b.y);
}
__device__ __forceinline__ void st_half4(__half* p, float4 v) {
    union { uint2 u; __half2 h[2]; } o;
    o.h[0] = __floats2half2_rn(v.x, v.y);
    o.h[1] = __floats2half2_rn(v.z, v.w);
    *reinterpret_cast<uint2*>(p) = o.u;
}
__device__ __forceinline__ float2 ld_half2f(const __half* p) {
    __half2 h = *reinterpret_cast<const __half2*>(p);
    return __half22float2(h);
}
__device__ __forceinline__ float eluf(float v) { return v > 0.f ? v : expm1f(v); }

// ---------------- fused prep: zero out / hraw / red / fcount / etouch + b3cum ----------------
__global__ void prepK(const float* __restrict__ b3, float4* __restrict__ out, int n4) {
    int i = blockIdx.x * blockDim.x + threadIdx.x;
    if (i < n4) out[i] = make_float4(0.f, 0.f, 0.f, 0.f);
    if (i < LAT * BN) g_hraw[i] = 0.f;
    if (i < 2 * BN)   g_red[i] = 0.f;
    if (i < NFN)      g_fcount[i] = 0;
    if (i < EE)       g_etouch[i] = 0;
    if (i >= EE) return;
    float a = 0.f;
    #pragma unroll
    for (int l = 0; l < LL; l++) { a += b3[l * EE + i]; g_b3cum[l * EE + i] = a; }
}

// ---------------- build buckets (p, e) + touched flags ----------------
__global__ void histK(const int* __restrict__ w3rows, const int* __restrict__ w3cols, int P) {
    int p = blockIdx.x * blockDim.x + threadIdx.x;
    if (p >= P) return;
    int fs = __ldg(&w3rows[p * 8]) >> 3;
    int e  = __ldg(&w3cols[p * 8]);
    g_etouch[e] = 1;
    int pos = atomicAdd(&g_fcount[fs], 1);
    if (pos < 64) g_fbucket[fs * 64 + pos] = make_int2(p, e);
}

// ---------------- transpose x : [b][n] -> [n][b] ----------------
__global__ void transposeK(const float* __restrict__ x) {
    __shared__ float t[32][33];
    int n0 = blockIdx.x * 32, b0 = blockIdx.y * 32;
    for (int i = threadIdx.y; i < 32; i += 8)
        t[i][threadIdx.x] = x[(b0 + i) * NN + n0 + threadIdx.x];
    __syncthreads();
    for (int i = threadIdx.y; i < 32; i += 8)
        g_xT[(n0 + i) * BN + b0 + threadIdx.x] = t[threadIdx.x][i];
}

// ---------------- gather into xe0 (+xe1 for never-touched rows) ----------------
__global__ void gatherK(const int* __restrict__ src) {
    int i = blockIdx.x * blockDim.x + threadIdx.x;   // i = e*32 + lane
    if (i >= EE * 32) return;
    int e = i >> 5, lane = i & 31;
    int s = src[e];
    float4 v = make_float4(0.f, 0.f, 0.f, 0.f);
    if (s >= NOMIC)
        v = *reinterpret_cast<const float4*>(&g_xT[s * BN + lane * 4]);
    *reinterpret_cast<float4*>(&g_xe0[e * BN + lane * 4]) = v;
    if (!g_etouch[e])
        *reinterpret_cast<float4*>(&g_xe1[e * BN + lane * 4]) = v;
}

// ---------------- gemm1: h_raw[j][b] += sum_k x[b][k] W1[k][j]  (split-K) ----------------
__global__ void gemm1K(const float* __restrict__ W1) {
    __shared__ float Wsm[240 * 20];
    int jt = blockIdx.x, ks = blockIdx.y;   // 5 x 15
    int t = threadIdx.x;                    // 128
    for (int idx = t; idx < 240 * 20; idx += 128) {
        int k = idx / 20, j = idx % 20;
        Wsm[idx] = W1[(ks * 240 + k) * LAT + jt * 20 + j];
    }
    __syncthreads();
    float acc[20];
    #pragma unroll
    for (int j = 0; j < 20; j++) acc[j] = 0.f;
    int b = t;
    const float* xp = &g_xT[(ks * 240) * BN + b];
    for (int k = 0; k < 240; k++) {
        float xv = xp[k * BN];
        #pragma unroll
        for (int j = 0; j < 20; j++) acc[j] += xv * Wsm[k * 20 + j];
    }
    #pragma unroll
    for (int j = 0; j < 20; j++)
        atomicAdd(&g_hraw[(jt * 20 + j) * BN + b], acc[j]);
}

__global__ void gemm1finK(const float* __restrict__ b_ae1) {
    int i = blockIdx.x * blockDim.x + threadIdx.x;   // 12800
    if (i >= LAT * BN) return;
    int j = i >> 7;
    g_hT[i] = eluf(g_hraw[i] + b_ae1[j]);
}

// ---------------- gemm2: z = hT W2 + b2, packed f32x2, z stored fp16 ----------------
__global__ void __launch_bounds__(128) gemm2K(const float* __restrict__ W2,
                                              const float* __restrict__ b2) {
    __shared__ unsigned long long Wp[100 * 32];   // 25.6KB
    int j0 = blockIdx.x * 64;
    int t = threadIdx.x, b = t;
    for (int idx = t; idx < 100 * 32; idx += 128) {
        int k = idx >> 5, j2 = idx & 31;
        Wp[idx] = *reinterpret_cast<const unsigned long long*>(&W2[(size_t)k * FCC + j0 + 2 * j2]);
    }
    __syncthreads();
    unsigned long long acc[32];
    #pragma unroll
    for (int j2 = 0; j2 < 32; j2++)
        acc[j2] = *reinterpret_cast<const unsigned long long*>(&b2[j0 + 2 * j2]);
    unsigned int wbase = (unsigned int)__cvta_generic_to_shared(Wp);
    for (int k = 0; k < 100; k++) {
        float hv = g_hT[k * BN + b];
        unsigned int hvi = __float_as_uint(hv);
        unsigned long long hv2;
        asm("mov.b64 %0, {%1,%1};" : "=l"(hv2) : "r"(hvi));
        #pragma unroll
        for (int j2 = 0; j2 < 32; j2 += 2) {
            unsigned long long w0, w1;
            asm("ld.shared.v2.b64 {%0,%1}, [%2];"
                : "=l"(w0), "=l"(w1) : "r"(wbase + (k * 32 + j2) * 8));
            asm("fma.rn.f32x2 %0, %1, %2, %0;" : "+l"(acc[j2])     : "l"(w0), "l"(hv2));
            asm("fma.rn.f32x2 %0, %1, %2, %0;" : "+l"(acc[j2 + 1]) : "l"(w1), "l"(hv2));
        }
    }
    float sum = 0.f, sq = 0.f;
    #pragma unroll
    for (int j2 = 0; j2 < 32; j2++) {
        unsigned int ulo, uhi;
        asm("mov.b64 {%0,%1}, %2;" : "=r"(ulo), "=r"(uhi) : "l"(acc[j2]));
        float lo = __uint_as_float(ulo), hi = __uint_as_float(uhi);
        int row = (j0 + 2 * j2) * BN + b;
        g_zh[row] = __float2half(lo);
        g_zh[row + BN] = __float2half(hi);
        sum += lo + hi;
        sq  += lo * lo + hi * hi;
    }
    atomicAdd(&g_red[b], sum);
    atomicAdd(&g_red[BN + b], sq);
}

// sigmoid(LN(z)) -> fp16 s; LN stats computed inline from raw sums
__global__ void sigK() {
    int i = blockIdx.x * blockDim.x + threadIdx.x;
    if (i >= FCC * 32) return;
    int lane = i & 31;
    const float inv = 1.f / (float)FCC;
    float4 z  = ld_half4(&g_zh[i * 4]);
    float4 sm = *reinterpret_cast<const float4*>(&g_red[lane * 4]);
    float4 sq = *reinterpret_cast<const float4*>(&g_red[BN + lane * 4]);
    float4 mu, rs;
    mu.x = sm.x * inv; mu.y = sm.y * inv; mu.z = sm.z * inv; mu.w = sm.w * inv;
    rs.x = rsqrtf(sq.x * inv - mu.x * mu.x + EPSV);
    rs.y = rsqrtf(sq.y * inv - mu.y * mu.y + EPSV);
    rs.z = rsqrtf(sq.z * inv - mu.z * mu.z + EPSV);
    rs.w = rsqrtf(sq.w * inv - mu.w * mu.w + EPSV);
    float4 v;
    v.x = 1.f / (1.f + __expf(-(z.x - mu.x) * rs.x));
    v.y = 1.f / (1.f + __expf(-(z.y - mu.y) * rs.y));
    v.z = 1.f / (1.f + __expf(-(z.z - mu.z) * rs.z));
    v.w = 1.f / (1.f + __expf(-(z.w - mu.w) * rs.w));
    st_half4(&g_s[i * 4], v);
}

// ---------------- fused layer: 512 thr, 8 functions, warp-pair batch split ----------------
// Warp w: function f0+(w&7), batch half (w>>3); lane owns float2 (2 batch elems).
__global__ void __launch_bounds__(512) layerK(const float* __restrict__ w1,
                                              const float* __restrict__ b1,
                                              const float* __restrict__ w3,
                                              int l) {
    __shared__ float ws[512];
    int t = threadIdx.x;            // 512
    int f0 = blockIdx.x * 8;
    ws[t] = w1[f0 * 64 + t];
    __syncthreads();
    int w = t >> 5, lane = t & 31;
    int fi = w & 7, half_ = w >> 3;
    int f = f0 + fi;
    int boff = half_ * 64 + lane * 2;        // batch offset in floats
    const float* xe_cur = (l & 1) ? g_xe1 : g_xe0;
    float*       xe_nxt = (l & 1) ? g_xe0 : g_xe1;
    const float* wf = &ws[fi * 64];
    float bc_l = 0.f;
    if (l > 0 && lane < 8) bc_l = __ldg(&g_b3cum[(l - 1) * EE + 8 * f + lane]);
    float2 a[8];
    #pragma unroll
    for (int c = 0; c < 8; c++) {
        float bv = __ldg(&b1[f * 8 + c]);
        a[c] = make_float2(bv, bv);
    }
    #pragma unroll
    for (int j = 0; j < 8; j++) {
        int e = 8 * f + j;
        float2 xv = *reinterpret_cast<const float2*>(&xe_cur[(size_t)e * BN + boff]);
        float bc = __shfl_sync(0xffffffffu, bc_l, j);
        xv.x += bc; xv.y += bc;
        #pragma unroll
        for (int c = 0; c < 8; c++) {
            float wv = wf[j * 8 + c];
            a[c].x += xv.x * wv;
            a[c].y += xv.y * wv;
        }
    }
    float2 mu = make_float2(0.f, 0.f);
    #pragma unroll
    for (int c = 0; c < 8; c++) { mu.x += a[c].x; mu.y += a[c].y; }
    mu.x *= 0.125f; mu.y *= 0.125f;
    float2 var = make_float2(0.f, 0.f);
    #pragma unroll
    for (int c = 0; c < 8; c++) {
        float dx = a[c].x - mu.x, dy = a[c].y - mu.y;
        var.x += dx * dx; var.y += dy * dy;
    }
    float2 rs;
    rs.x = rsqrtf(var.x * 0.125f + EPSV);
    rs.y = rsqrtf(var.y * 0.125f + EPSV);
    #pragma unroll
    for (int c = 0; c < 8; c++) {
        int row = f * 8 + c;
        float2 sv = ld_half2f(&g_s[(size_t)row * BN + boff]);
        a[c].x = eluf((a[c].x - mu.x) * rs.x * sv.x);
        a[c].y = eluf((a[c].y - mu.y) * rs.y * sv.y);
    }
    // scatter this function's out-edges (batch half only)
    int cnt = g_fcount[f];
    if (cnt > 64) cnt = 64;
    for (int i = 0; i < cnt; i++) {
        int2 pe = g_fbucket[f * 64 + i];
        int p = pe.x, e = pe.y;
        float4 w0  = *reinterpret_cast<const float4*>(&w3[p * 8]);
        float4 w1v = *reinterpret_cast<const float4*>(&w3[p * 8 + 4]);
        float2 acc = *reinterpret_cast<const float2*>(&xe_cur[(size_t)e * BN + boff]);
        acc.x += a[0].x * w0.x + a[1].x * w0.y + a[2].x * w0.z + a[3].x * w0.w
               + a[4].x * w1v.x + a[5].x * w1v.y + a[6].x * w1v.z + a[7].x * w1v.w;
        acc.y += a[0].y * w0.x + a[1].y * w0.y + a[2].y * w0.z + a[3].y * w0.w
               + a[4].y * w1v.x + a[5].y * w1v.y + a[6].y * w1v.z + a[7].y * w1v.w;
        *reinterpret_cast<float2*>(&xe_nxt[(size_t)e * BN + boff]) = acc;
    }
}

// ---------------- final: only out-edges survive the mask; result in xe0 ----------------
__global__ void finalK(const int* __restrict__ dst, float* __restrict__ out) {
    int i = blockIdx.x * blockDim.x + threadIdx.x;   // 1000*128
    if (i >= 1000 * BN) return;
    int k = i >> 7, b = i & 127;
    int e = FCC + k;
    float v = (g_xe0[(size_t)e * BN + b] + g_b3cum[3 * EE + e]) * 0.25f;
    out[b * NN + dst[e]] = v;
}

// ---------------- launch (single stream) ----------------
extern "C" void kernel_launch(void* const* d_in, const int* in_sizes, int n_in,
                              void* d_out, int out_size) {
    const float* x       = (const float*)d_in[0];
    const float* W_ae1   = (const float*)d_in[1];
    const float* b_ae1   = (const float*)d_in[2];
    const float* W_ae2   = (const float*)d_in[3];
    const float* b_ae2   = (const float*)d_in[4];
    const float* w1_vals = (const float*)d_in[5];
    const float* b1      = (const float*)d_in[6];
    const float* w3_vals = (const float*)d_in[7];
    const float* b3      = (const float*)d_in[8];
    const int*   src     = (const int*)  d_in[9];
    const int*   dst     = (const int*)  d_in[10];
    const int*   w3_rows = (const int*)  d_in[13];
    const int*   w3_cols = (const int*)  d_in[14];
    float* out = (float*)d_out;

    int nnz1 = in_sizes[5] / LL;
    int nnz3 = in_sizes[7] / LL;
    int P = nnz3 / 8;
    int n4 = out_size / 4;
    int gridPrep = (n4 + 255) / 256;
    if (gridPrep < (EE + 255) / 256) gridPrep = (EE + 255) / 256;

    prepK<<<gridPrep, 256>>>(b3, (float4*)out, n4);
    histK<<<(P + 255) / 256, 256>>>(w3_rows, w3_cols, P);
    transposeK<<<dim3(NN / 32, BN / 32), dim3(32, 8)>>>(x);
    gatherK<<<(EE * 32 + 255) / 256, 256>>>(src);

    gemm1K<<<dim3(5, 15), 128>>>(W_ae1);
    gemm1finK<<<(LAT * BN + 127) / 128, 128>>>(b_ae1);
    gemm2K<<<FCC / 64, 128>>>(W_ae2, b_ae2);
    sigK<<<(FCC * 32 + 255) / 256, 256>>>();

    for (int l = 0; l < LL; l++)
        layerK<<<NFN / 8, 512>>>(w1_vals + (size_t)l * nnz1,
                                 b1 + (size_t)l * FCC,
                                 w3_vals + (size_t)l * nnz3, l);

    finalK<<<(1000 * BN) / 256, 256>>>(dst, out);
}

// round 11
// speedup vs baseline: 1.0756x; 1.0756x over previous
#include <cuda_runtime.h>
#include <cuda_fp16.h>
#include <cstdint>

#define BN    128
#define NN    12000
#define NOMIC 3600
#define NFN   7000
#define FCC   56000
#define EE    57000
#define LL    4
#define LAT   100
#define KPAD  112
#define HPAD  120
#define EPSV  1e-5f

// ---------------- scratch (device globals; no allocation allowed) ----------------
__device__ float  g_xT[NN * BN];          // x transposed [n][b]
__device__ float  g_xe[EE * BN];          // edge state [e][b] (in-place RMW)
__device__ __half g_zh[FCC * BN];         // z (pre-sigmoid) fp16
__device__ __half g_s [FCC * BN];         // s = sigmoid(LN(z))  fp16
__device__ __half g_hfc[FCC * BN];        // hfc fp16
__device__ __half g_W2h[KPAD * FCC];      // W2 fp16, padded k rows (>=100 are zero)
__device__ __half g_hh[BN * HPAD];        // elu(h) fp16, b-major, padded k (>=100 zero)
__device__ float  g_b3cum[LL * EE];       // cumulative b3 sums
__device__ float  g_hraw[LAT * BN];       // gemm1 accumulator [j][b]
__device__ float  g_red [2 * BN];         // LN sum/sumsq (raw)

// ---------------- helpers ----------------
__device__ __forceinline__ float4 ld_half4(const __half* p) {
    union { uint2 u; __half2 h[2]; } v;
    v.u = *reinterpret_cast<const uint2*>(p);
    float2 a = __half22float2(v.h[0]);
    float2 b = __half22float2(v.h[1]);
    return make_float4(a.x, a.y, b.x, b.y);
}
__device__ __forceinline__ void st_half4(__half* p, float4 v) {
    union { uint2 u; __half2 h[2]; } o;
    o.h[0] = __floats2half2_rn(v.x, v.y);
    o.h[1] = __floats2half2_rn(v.z, v.w);
    *reinterpret_cast<uint2*>(p) = o.u;
}
__device__ __forceinline__ float eluf(float v) { return v > 0.f ? v : expm1f(v); }
__device__ __forceinline__ unsigned packh(__half lo, __half hi) {
    __half2 h = __halves2half2(lo, hi);
    return *reinterpret_cast<unsigned*>(&h);
}

// ---------------- fused prep: zero out/hraw/red + b3cum + W2->fp16 (padded) ----------------
__global__ void prepK(const float* __restrict__ b3, const float* __restrict__ W2,
                      float4* __restrict__ out, int n4) {
    int i = blockIdx.x * blockDim.x + threadIdx.x;
    if (i < n4) out[i] = make_float4(0.f, 0.f, 0.f, 0.f);
    if (i < LAT * BN) g_hraw[i] = 0.f;
    if (i < 2 * BN)   g_red[i] = 0.f;
    if (i < EE) {
        float a = 0.f;
        #pragma unroll
        for (int l = 0; l < LL; l++) { a += b3[l * EE + i]; g_b3cum[l * EE + i] = a; }
    }
    // W2 conversion: 4 halfs per thread over padded [KPAD][FCC]
    if (i < (KPAD * FCC) / 4) {
        int k = (i * 4) / FCC;
        uint2 o;
        if (k < LAT) {
            float4 w = reinterpret_cast<const float4*>(W2)[i];
            __half2 h0 = __floats2half2_rn(w.x, w.y);
            __half2 h1 = __floats2half2_rn(w.z, w.w);
            o.x = *reinterpret_cast<unsigned*>(&h0);
            o.y = *reinterpret_cast<unsigned*>(&h1);
        } else {
            o.x = 0u; o.y = 0u;
        }
        reinterpret_cast<uint2*>(g_W2h)[i] = o;
    }
}

// ---------------- transpose x : [b][n] -> [n][b] ----------------
__global__ void transposeK(const float* __restrict__ x) {
    __shared__ float t[32][33];
    int n0 = blockIdx.x * 32, b0 = blockIdx.y * 32;
    for (int i = threadIdx.y; i < 32; i += 8)
        t[i][threadIdx.x] = x[(b0 + i) * NN + n0 + threadIdx.x];
    __syncthreads();
    for (int i = threadIdx.y; i < 32; i += 8)
        g_xT[(n0 + i) * BN + b0 + threadIdx.x] = t[threadIdx.x][i];
}

// ---------------- initial edge gather (float4, omic columns zeroed) ----------------
__global__ void gatherK(const int* __restrict__ src) {
    int i = blockIdx.x * blockDim.x + threadIdx.x;   // i = e*32 + lane
    if (i >= EE * 32) return;
    int e = i >> 5, lane = i & 31;
    int s = src[e];
    float4 v = make_float4(0.f, 0.f, 0.f, 0.f);
    if (s >= NOMIC)
        v = *reinterpret_cast<const float4*>(&g_xT[s * BN + lane * 4]);
    *reinterpret_cast<float4*>(&g_xe[e * BN + lane * 4]) = v;
}

// ---------------- gemm1: h_raw[j][b] += sum_k x[b][k] W1[k][j]  (split-K) ----------------
__global__ void gemm1K(const float* __restrict__ W1) {
    __shared__ float Wsm[240 * 20];
    int jt = blockIdx.x, ks = blockIdx.y;   // 5 x 15
    int t = threadIdx.x;                    // 128
    for (int idx = t; idx < 240 * 20; idx += 128) {
        int k = idx / 20, j = idx % 20;
        Wsm[idx] = W1[(ks * 240 + k) * LAT + jt * 20 + j];
    }
    __syncthreads();
    float acc[20];
    #pragma unroll
    for (int j = 0; j < 20; j++) acc[j] = 0.f;
    int b = t;
    const float* xp = &g_xT[(ks * 240) * BN + b];
    for (int k = 0; k < 240; k++) {
        float xv = xp[k * BN];
        #pragma unroll
        for (int j = 0; j < 20; j++) acc[j] += xv * Wsm[k * 20 + j];
    }
    #pragma unroll
    for (int j = 0; j < 20; j++)
        atomicAdd(&g_hraw[(jt * 20 + j) * BN + b], acc[j]);
}

// elu(hraw + bias) -> g_hh [b][HPAD] fp16 (zero-padded k)
__global__ void gemm1finK(const float* __restrict__ b_ae1) {
    int i = blockIdx.x * blockDim.x + threadIdx.x;   // BN*HPAD
    if (i >= BN * HPAD) return;
    int b = i / HPAD, k = i % HPAD;
    float v = 0.f;
    if (k < LAT) v = eluf(g_hraw[k * BN + b] + b_ae1[k]);
    g_hh[i] = __float2half(v);
}

// ---------------- gemm2 via fp16 tensor cores: z = W2^T h + b2 ----------------
// Block: 256 thr (8 warps). j-tile 64, full b=128. Warp: jsub = w&3 (16 j), bhalf = w>>2 (64 b).
__global__ void __launch_bounds__(256) gemm2K(const float* __restrict__ b2) {
    __shared__ __half hh[BN * HPAD];        // 30720 B
    __shared__ float sSum[BN], sSq[BN];
    int t = threadIdx.x;
    {
        const uint4* s = reinterpret_cast<const uint4*>(g_hh);
        uint4* d = reinterpret_cast<uint4*>(hh);
        #pragma unroll
        for (int i = 0; i < 8; i++) {
            int idx = t + i * 256;
            if (idx < (BN * HPAD) / 8) d[idx] = s[idx];
        }
    }
    if (t < BN) { sSum[t] = 0.f; sSq[t] = 0.f; }
    __syncthreads();

    int w = t >> 5, lane = t & 31;
    int g = lane >> 2, tg = lane & 3;
    int jsub = w & 3, bhalf = w >> 2;
    int j0 = blockIdx.x * 64 + jsub * 16;
    int jr0 = j0 + g, jr1 = j0 + g + 8;

    float c[8][4];
    #pragma unroll
    for (int nt = 0; nt < 8; nt++)
        c[nt][0] = c[nt][1] = c[nt][2] = c[nt][3] = 0.f;

    #pragma unroll
    for (int ks = 0; ks < 7; ks++) {
        int k = ks * 16 + 2 * tg;
        unsigned a0 = packh(g_W2h[(size_t)k * FCC + jr0],       g_W2h[(size_t)(k + 1) * FCC + jr0]);
        unsigned a1 = packh(g_W2h[(size_t)k * FCC + jr1],       g_W2h[(size_t)(k + 1) * FCC + jr1]);
        unsigned a2 = packh(g_W2h[(size_t)(k + 8) * FCC + jr0], g_W2h[(size_t)(k + 9) * FCC + jr0]);
        unsigned a3 = packh(g_W2h[(size_t)(k + 8) * FCC + jr1], g_W2h[(size_t)(k + 9) * FCC + jr1]);
        #pragma unroll
        for (int nt = 0; nt < 8; nt++) {
            int nb = bhalf * 64 + nt * 8 + g;
            unsigned b0 = *reinterpret_cast<const unsigned*>(&hh[nb * HPAD + k]);
            unsigned b1 = *reinterpret_cast<const unsigned*>(&hh[nb * HPAD + k + 8]);
            asm volatile(
                "mma.sync.aligned.m16n8k16.row.col.f32.f16.f16.f32 "
                "{%0,%1,%2,%3}, {%4,%5,%6,%7}, {%8,%9}, {%0,%1,%2,%3};"
                : "+f"(c[nt][0]), "+f"(c[nt][1]), "+f"(c[nt][2]), "+f"(c[nt][3])
                : "r"(a0), "r"(a1), "r"(a2), "r"(a3), "r"(b0), "r"(b1));
        }
    }

    float bias0 = b2[jr0], bias1 = b2[jr1];
    #pragma unroll
    for (int nt = 0; nt < 8; nt++) {
        int bc = bhalf * 64 + nt * 8 + 2 * tg;
        float v0 = c[nt][0] + bias0, v1 = c[nt][1] + bias0;
        float v2 = c[nt][2] + bias1, v3 = c[nt][3] + bias1;
        *reinterpret_cast<__half2*>(&g_zh[(size_t)jr0 * BN + bc]) = __floats2half2_rn(v0, v1);
        *reinterpret_cast<__half2*>(&g_zh[(size_t)jr1 * BN + bc]) = __floats2half2_rn(v2, v3);
        atomicAdd(&sSum[bc],     v0 + v2);
        atomicAdd(&sSq[bc],      v0 * v0 + v2 * v2);
        atomicAdd(&sSum[bc + 1], v1 + v3);
        atomicAdd(&sSq[bc + 1],  v1 * v1 + v3 * v3);
    }
    __syncthreads();
    if (t < BN) {
        atomicAdd(&g_red[t], sSum[t]);
        atomicAdd(&g_red[BN + t], sSq[t]);
    }
}

// sigmoid(LN(z)) -> fp16 s; LN stats inline from raw sums
__global__ void sigK() {
    int i = blockIdx.x * blockDim.x + threadIdx.x;
    if (i >= FCC * 32) return;
    int lane = i & 31;
    const float inv = 1.f / (float)FCC;
    float4 z  = ld_half4(&g_zh[i * 4]);
    float4 sm = *reinterpret_cast<const float4*>(&g_red[lane * 4]);
    float4 sq = *reinterpret_cast<const float4*>(&g_red[BN + lane * 4]);
    float4 mu, rs;
    mu.x = sm.x * inv; mu.y = sm.y * inv; mu.z = sm.z * inv; mu.w = sm.w * inv;
    rs.x = rsqrtf(sq.x * inv - mu.x * mu.x + EPSV);
    rs.y = rsqrtf(sq.y * inv - mu.y * mu.y + EPSV);
    rs.z = rsqrtf(sq.z * inv - mu.z * mu.z + EPSV);
    rs.w = rsqrtf(sq.w * inv - mu.w * mu.w + EPSV);
    float4 v;
    v.x = 1.f / (1.f + __expf(-(z.x - mu.x) * rs.x));
    v.y = 1.f / (1.f + __expf(-(z.y - mu.y) * rs.y));
    v.z = 1.f / (1.f + __expf(-(z.z - mu.z) * rs.z));
    v.w = 1.f / (1.f + __expf(-(z.w - mu.w) * rs.w));
    st_half4(&g_s[i * 4], v);
}

// ---------------- spmm1 + groupLN + s*elu (warp per function, float4 over b) ----------------
__global__ void __launch_bounds__(256) spmm1K(const float* __restrict__ w1,
                                              const float* __restrict__ b1,
                                              int l) {
    __shared__ float ws[512];
    int t = threadIdx.x;            // 256
    int f0 = blockIdx.x * 8;
    ws[t]       = w1[f0 * 64 + t];
    ws[t + 256] = w1[f0 * 64 + 256 + t];
    __syncthreads();
    int w = t >> 5, lane = t & 31;
    int f = f0 + w;
    const float* wf = &ws[w * 64];
    float bc_l = 0.f;
    if (l > 0 && lane < 8) bc_l = __ldg(&g_b3cum[(l - 1) * EE + 8 * f + lane]);
    float4 a[8];
    #pragma unroll
    for (int c = 0; c < 8; c++) {
        float bv = __ldg(&b1[f * 8 + c]);
        a[c] = make_float4(bv, bv, bv, bv);
    }
    #pragma unroll
    for (int j = 0; j < 8; j++) {
        int e = 8 * f + j;
        float4 xv = *reinterpret_cast<const float4*>(&g_xe[e * BN + lane * 4]);
        float bc = __shfl_sync(0xffffffffu, bc_l, j);
        xv.x += bc; xv.y += bc; xv.z += bc; xv.w += bc;
        #pragma unroll
        for (int c = 0; c < 8; c++) {
            float wv = wf[j * 8 + c];
            a[c].x += xv.x * wv; a[c].y += xv.y * wv;
            a[c].z += xv.z * wv; a[c].w += xv.w * wv;
        }
    }
    float4 mu = make_float4(0.f, 0.f, 0.f, 0.f);
    #pragma unroll
    for (int c = 0; c < 8; c++) { mu.x += a[c].x; mu.y += a[c].y; mu.z += a[c].z; mu.w += a[c].w; }
    mu.x *= 0.125f; mu.y *= 0.125f; mu.z *= 0.125f; mu.w *= 0.125f;
    float4 var = make_float4(0.f, 0.f, 0.f, 0.f);
    #pragma unroll
    for (int c = 0; c < 8; c++) {
        float dx = a[c].x - mu.x, dy = a[c].y - mu.y, dz = a[c].z - mu.z, dw = a[c].w - mu.w;
        var.x += dx * dx; var.y += dy * dy; var.z += dz * dz; var.w += dw * dw;
    }
    float4 rs;
    rs.x = rsqrtf(var.x * 0.125f + EPSV);
    rs.y = rsqrtf(var.y * 0.125f + EPSV);
    rs.z = rsqrtf(var.z * 0.125f + EPSV);
    rs.w = rsqrtf(var.w * 0.125f + EPSV);
    #pragma unroll
    for (int c = 0; c < 8; c++) {
        int row = f * 8 + c;
        float4 sv = ld_half4(&g_s[row * BN + lane * 4]);
        float4 v;
        v.x = eluf((a[c].x - mu.x) * rs.x * sv.x);
        v.y = eluf((a[c].y - mu.y) * rs.y * sv.y);
        v.z = eluf((a[c].z - mu.z) * rs.z * sv.z);
        v.w = eluf((a[c].w - mu.w) * rs.w * sv.w);
        st_half4(&g_hfc[row * BN + lane * 4], v);
    }
}

// ---------------- spmm3 (warp per fe-edge, fully parallel, float4 xe RMW) ----------------
__global__ void __launch_bounds__(256) spmm3K(const float* __restrict__ w3,
                                              const int* __restrict__ w3rows,
                                              const int* __restrict__ w3cols,
                                              int P) {
    int idx = blockIdx.x * blockDim.x + threadIdx.x;
    int p = idx >> 5, lane = idx & 31;
    if (p >= P) return;
    int fs = __ldg(&w3rows[p * 8]) >> 3;
    int e  = __ldg(&w3cols[p * 8]);
    float4 w0  = *reinterpret_cast<const float4*>(&w3[p * 8]);
    float4 w1v = *reinterpret_cast<const float4*>(&w3[p * 8 + 4]);
    float* xp = &g_xe[(size_t)e * BN + lane * 4];
    float4 acc = *reinterpret_cast<const float4*>(xp);
    const __half* hb = &g_hfc[(size_t)(fs * 8) * BN + lane * 4];
    float4 hv[8];
    #pragma unroll
    for (int c = 0; c < 8; c++) hv[c] = ld_half4(hb + (size_t)c * BN);
    acc.x += hv[0].x * w0.x + hv[1].x * w0.y + hv[2].x * w0.z + hv[3].x * w0.w
           + hv[4].x * w1v.x + hv[5].x * w1v.y + hv[6].x * w1v.z + hv[7].x * w1v.w;
    acc.y += hv[0].y * w0.x + hv[1].y * w0.y + hv[2].y * w0.z + hv[3].y * w0.w
           + hv[4].y * w1v.x + hv[5].y * w1v.y + hv[6].y * w1v.z + hv[7].y * w1v.w;
    acc.z += hv[0].z * w0.x + hv[1].z * w0.y + hv[2].z * w0.z + hv[3].z * w0.w
           + hv[4].z * w1v.x + hv[5].z * w1v.y + hv[6].z * w1v.z + hv[7].z * w1v.w;
    acc.w += hv[0].w * w0.x + hv[1].w * w0.y + hv[2].w * w0.z + hv[3].w * w0.w
           + hv[4].w * w1v.x + hv[5].w * w1v.y + hv[6].w * w1v.z + hv[7].w * w1v.w;
    *reinterpret_cast<float4*>(xp) = acc;
}

// ---------------- final: only out-edges survive the mask ----------------
__global__ void finalK(const int* __restrict__ dst, float* __restrict__ out) {
    int i = blockIdx.x * blockDim.x + threadIdx.x;   // 1000*128
    if (i >= 1000 * BN) return;
    int k = i >> 7, b = i & 127;
    int e = FCC + k;
    float v = (g_xe[(size_t)e * BN + b] + g_b3cum[3 * EE + e]) * 0.25f;
    out[b * NN + dst[e]] = v;
}

// ---------------- launch (single stream) ----------------
extern "C" void kernel_launch(void* const* d_in, const int* in_sizes, int n_in,
                              void* d_out, int out_size) {
    const float* x       = (const float*)d_in[0];
    const float* W_ae1   = (const float*)d_in[1];
    const float* b_ae1   = (const float*)d_in[2];
    const float* W_ae2   = (const float*)d_in[3];
    const float* b_ae2   = (const float*)d_in[4];
    const float* w1_vals = (const float*)d_in[5];
    const float* b1      = (const float*)d_in[6];
    const float* w3_vals = (const float*)d_in[7];
    const float* b3      = (const float*)d_in[8];
    const int*   src     = (const int*)  d_in[9];
    const int*   dst     = (const int*)  d_in[10];
    const int*   w3_rows = (const int*)  d_in[13];
    const int*   w3_cols = (const int*)  d_in[14];
    float* out = (float*)d_out;

    int nnz1 = in_sizes[5] / LL;
    int nnz3 = in_sizes[7] / LL;
    int P = nnz3 / 8;
    int n4 = out_size / 4;
    int prepN = (KPAD * FCC) / 4;            // 1,568,000 dominates
    if (prepN < n4) prepN = n4;
    if (prepN < EE) prepN = EE;

    prepK<<<(prepN + 255) / 256, 256>>>(b3, W_ae2, (float4*)out, n4);
    transposeK<<<dim3(NN / 32, BN / 32), dim3(32, 8)>>>(x);
    gatherK<<<(EE * 32 + 255) / 256, 256>>>(src);

    gemm1K<<<dim3(5, 15), 128>>>(W_ae1);
    gemm1finK<<<(BN * HPAD + 255) / 256, 256>>>(b_ae1);
    gemm2K<<<FCC / 64, 256>>>(b_ae2);
    sigK<<<(FCC * 32 + 255) / 256, 256>>>();

    for (int l = 0; l < LL; l++) {
        spmm1K<<<NFN / 8, 256>>>(w1_vals + (size_t)l * nnz1, b1 + (size_t)l * FCC, l);
        spmm3K<<<(P * 32 + 255) / 256, 256>>>(w3_vals + (size_t)l * nnz3, w3_rows, w3_cols, P);
    }

    finalK<<<(1000 * BN) / 256, 256>>>(dst, out);
}

// round 12
// speedup vs baseline: 1.1848x; 1.1015x over previous
#include <cuda_runtime.h>
#include <cuda_fp16.h>
#include <cstdint>

#define BN    128
#define NN    12000
#define NOMIC 3600
#define NFN   7000
#define FCC   56000
#define EE    57000
#define LL    4
#define LAT   100
#define KPAD  112
#define HPAD  120
#define EPSV  1e-5f
#define KSPL  60          // gemm1 k-splits
#define KCH   60          // k per split (60*60=3600)

// ---------------- scratch (device globals; no allocation allowed) ----------------
__device__ float  g_xT[NN * BN];          // x transposed [n][b]
__device__ float  g_xe[EE * BN];          // edge state [e][b] (in-place RMW)
__device__ __half g_zh[FCC * BN];         // z (pre-sigmoid) fp16
__device__ __half g_s [FCC * BN];         // s = sigmoid(LN(z))  fp16
__device__ __half g_hfc[FCC * BN];        // hfc fp16
__device__ __half g_W2h[KPAD * FCC];      // W2 fp16, padded k rows (>=100 are zero)
__device__ __half g_hh[BN * HPAD];        // elu(h) fp16, b-major, padded k (>=100 zero)
__device__ float  g_b3cum[LL * EE];       // cumulative b3 sums
__device__ float  g_hraw[LAT * BN];       // gemm1 accumulator [j][b]
__device__ float  g_red [2 * BN];         // LN sum/sumsq (raw)

// ---------------- helpers ----------------
__device__ __forceinline__ float4 ld_half4(const __half* p) {
    union { uint2 u; __half2 h[2]; } v;
    v.u = *reinterpret_cast<const uint2*>(p);
    float2 a = __half22float2(v.h[0]);
    float2 b = __half22float2(v.h[1]);
    return make_float4(a.x, a.y, b.x, b.y);
}
__device__ __forceinline__ void st_half4(__half* p, float4 v) {
    union { uint2 u; __half2 h[2]; } o;
    o.h[0] = __floats2half2_rn(v.x, v.y);
    o.h[1] = __floats2half2_rn(v.z, v.w);
    *reinterpret_cast<uint2*>(p) = o.u;
}
__device__ __forceinline__ float eluf(float v) { return v > 0.f ? v : expm1f(v); }
__device__ __forceinline__ unsigned packh(__half lo, __half hi) {
    __half2 h = __halves2half2(lo, hi);
    return *reinterpret_cast<unsigned*>(&h);
}

// ---------------- fused prep: zero out/hraw/red + b3cum + W2->fp16 (padded) ----------------
__global__ void prepK(const float* __restrict__ b3, const float* __restrict__ W2,
                      float4* __restrict__ out, int n4) {
    int i = blockIdx.x * blockDim.x + threadIdx.x;
    if (i < n4) out[i] = make_float4(0.f, 0.f, 0.f, 0.f);
    if (i < LAT * BN) g_hraw[i] = 0.f;
    if (i < 2 * BN)   g_red[i] = 0.f;
    if (i < EE) {
        float a = 0.f;
        #pragma unroll
        for (int l = 0; l < LL; l++) { a += b3[l * EE + i]; g_b3cum[l * EE + i] = a; }
    }
    if (i < (KPAD * FCC) / 4) {
        int k = (i * 4) / FCC;
        uint2 o;
        if (k < LAT) {
            float4 w = reinterpret_cast<const float4*>(W2)[i];
            __half2 h0 = __floats2half2_rn(w.x, w.y);
            __half2 h1 = __floats2half2_rn(w.z, w.w);
            o.x = *reinterpret_cast<unsigned*>(&h0);
            o.y = *reinterpret_cast<unsigned*>(&h1);
        } else {
            o.x = 0u; o.y = 0u;
        }
        reinterpret_cast<uint2*>(g_W2h)[i] = o;
    }
}

// ---------------- transpose x : [b][n] -> [n][b] ----------------
__global__ void transposeK(const float* __restrict__ x) {
    __shared__ float t[32][33];
    int n0 = blockIdx.x * 32, b0 = blockIdx.y * 32;
    for (int i = threadIdx.y; i < 32; i += 8)
        t[i][threadIdx.x] = x[(b0 + i) * NN + n0 + threadIdx.x];
    __syncthreads();
    for (int i = threadIdx.y; i < 32; i += 8)
        g_xT[(n0 + i) * BN + b0 + threadIdx.x] = t[threadIdx.x][i];
}

// ---------------- initial edge gather (float4, omic columns zeroed) ----------------
__global__ void gatherK(const int* __restrict__ src) {
    int i = blockIdx.x * blockDim.x + threadIdx.x;   // i = e*32 + lane
    if (i >= EE * 32) return;
    int e = i >> 5, lane = i & 31;
    int s = src[e];
    float4 v = make_float4(0.f, 0.f, 0.f, 0.f);
    if (s >= NOMIC)
        v = *reinterpret_cast<const float4*>(&g_xT[s * BN + lane * 4]);
    *reinterpret_cast<float4*>(&g_xe[e * BN + lane * 4]) = v;
}

// ---------------- gemm1: fine split-K for occupancy ----------------
__global__ void gemm1K(const float* __restrict__ W1) {
    __shared__ float Wsm[KCH * 20];
    int jt = blockIdx.x, ks = blockIdx.y;   // 5 x KSPL
    int t = threadIdx.x;                    // 128
    for (int idx = t; idx < KCH * 20; idx += 128) {
        int k = idx / 20, j = idx % 20;
        Wsm[idx] = W1[(ks * KCH + k) * LAT + jt * 20 + j];
    }
    __syncthreads();
    float acc[20];
    #pragma unroll
    for (int j = 0; j < 20; j++) acc[j] = 0.f;
    int b = t;
    const float* xp = &g_xT[(ks * KCH) * BN + b];
    #pragma unroll 4
    for (int k = 0; k < KCH; k++) {
        float xv = xp[k * BN];
        #pragma unroll
        for (int j = 0; j < 20; j++) acc[j] += xv * Wsm[k * 20 + j];
    }
    #pragma unroll
    for (int j = 0; j < 20; j++)
        atomicAdd(&g_hraw[(jt * 20 + j) * BN + b], acc[j]);
}

// elu(hraw + bias) -> g_hh [b][HPAD] fp16 (zero-padded k)
__global__ void gemm1finK(const float* __restrict__ b_ae1) {
    int i = blockIdx.x * blockDim.x + threadIdx.x;   // BN*HPAD
    if (i >= BN * HPAD) return;
    int b = i / HPAD, k = i % HPAD;
    float v = 0.f;
    if (k < LAT) v = eluf(g_hraw[k * BN + b] + b_ae1[k]);
    g_hh[i] = __float2half(v);
}

// ---------------- gemm2 via fp16 tensor cores: z = W2^T h + b2 ----------------
__global__ void __launch_bounds__(256) gemm2K(const float* __restrict__ b2) {
    __shared__ __half hh[BN * HPAD];        // 30720 B
    __shared__ float sSum[BN], sSq[BN];
    int t = threadIdx.x;
    {
        const uint4* s = reinterpret_cast<const uint4*>(g_hh);
        uint4* d = reinterpret_cast<uint4*>(hh);
        #pragma unroll
        for (int i = 0; i < 8; i++) {
            int idx = t + i * 256;
            if (idx < (BN * HPAD) / 8) d[idx] = s[idx];
        }
    }
    if (t < BN) { sSum[t] = 0.f; sSq[t] = 0.f; }
    __syncthreads();

    int w = t >> 5, lane = t & 31;
    int g = lane >> 2, tg = lane & 3;
    int jsub = w & 3, bhalf = w >> 2;
    int j0 = blockIdx.x * 64 + jsub * 16;
    int jr0 = j0 + g, jr1 = j0 + g + 8;

    float c[8][4];
    #pragma unroll
    for (int nt = 0; nt < 8; nt++)
        c[nt][0] = c[nt][1] = c[nt][2] = c[nt][3] = 0.f;

    #pragma unroll
    for (int ks = 0; ks < 7; ks++) {
        int k = ks * 16 + 2 * tg;
        unsigned a0 = packh(g_W2h[(size_t)k * FCC + jr0],       g_W2h[(size_t)(k + 1) * FCC + jr0]);
        unsigned a1 = packh(g_W2h[(size_t)k * FCC + jr1],       g_W2h[(size_t)(k + 1) * FCC + jr1]);
        unsigned a2 = packh(g_W2h[(size_t)(k + 8) * FCC + jr0], g_W2h[(size_t)(k + 9) * FCC + jr0]);
        unsigned a3 = packh(g_W2h[(size_t)(k + 8) * FCC + jr1], g_W2h[(size_t)(k + 9) * FCC + jr1]);
        #pragma unroll
        for (int nt = 0; nt < 8; nt++) {
            int nb = bhalf * 64 + nt * 8 + g;
            unsigned b0 = *reinterpret_cast<const unsigned*>(&hh[nb * HPAD + k]);
            unsigned b1 = *reinterpret_cast<const unsigned*>(&hh[nb * HPAD + k + 8]);
            asm volatile(
                "mma.sync.aligned.m16n8k16.row.col.f32.f16.f16.f32 "
                "{%0,%1,%2,%3}, {%4,%5,%6,%7}, {%8,%9}, {%0,%1,%2,%3};"
                : "+f"(c[nt][0]), "+f"(c[nt][1]), "+f"(c[nt][2]), "+f"(c[nt][3])
                : "r"(a0), "r"(a1), "r"(a2), "r"(a3), "r"(b0), "r"(b1));
        }
    }

    float bias0 = b2[jr0], bias1 = b2[jr1];
    #pragma unroll
    for (int nt = 0; nt < 8; nt++) {
        int bc = bhalf * 64 + nt * 8 + 2 * tg;
        float v0 = c[nt][0] + bias0, v1 = c[nt][1] + bias0;
        float v2 = c[nt][2] + bias1, v3 = c[nt][3] + bias1;
        *reinterpret_cast<__half2*>(&g_zh[(size_t)jr0 * BN + bc]) = __floats2half2_rn(v0, v1);
        *reinterpret_cast<__half2*>(&g_zh[(size_t)jr1 * BN + bc]) = __floats2half2_rn(v2, v3);
        atomicAdd(&sSum[bc],     v0 + v2);
        atomicAdd(&sSq[bc],      v0 * v0 + v2 * v2);
        atomicAdd(&sSum[bc + 1], v1 + v3);
        atomicAdd(&sSq[bc + 1],  v1 * v1 + v3 * v3);
    }
    __syncthreads();
    if (t < BN) {
        atomicAdd(&g_red[t], sSum[t]);
        atomicAdd(&g_red[BN + t], sSq[t]);
    }
}

// sigmoid(LN(z)) -> fp16 s; LN stats inline from raw sums
__global__ void sigK() {
    int i = blockIdx.x * blockDim.x + threadIdx.x;
    if (i >= FCC * 32) return;
    int lane = i & 31;
    const float inv = 1.f / (float)FCC;
    float4 z  = ld_half4(&g_zh[i * 4]);
    float4 sm = *reinterpret_cast<const float4*>(&g_red[lane * 4]);
    float4 sq = *reinterpret_cast<const float4*>(&g_red[BN + lane * 4]);
    float4 mu, rs;
    mu.x = sm.x * inv; mu.y = sm.y * inv; mu.z = sm.z * inv; mu.w = sm.w * inv;
    rs.x = rsqrtf(sq.x * inv - mu.x * mu.x + EPSV);
    rs.y = rsqrtf(sq.y * inv - mu.y * mu.y + EPSV);
    rs.z = rsqrtf(sq.z * inv - mu.z * mu.z + EPSV);
    rs.w = rsqrtf(sq.w * inv - mu.w * mu.w + EPSV);
    float4 v;
    v.x = 1.f / (1.f + __expf(-(z.x - mu.x) * rs.x));
    v.y = 1.f / (1.f + __expf(-(z.y - mu.y) * rs.y));
    v.z = 1.f / (1.f + __expf(-(z.z - mu.z) * rs.z));
    v.w = 1.f / (1.f + __expf(-(z.w - mu.w) * rs.w));
    st_half4(&g_s[i * 4], v);
}

// ---------------- spmm1 + groupLN + s*elu (warp per function, float4 over b) ----------------
__global__ void __launch_bounds__(256) spmm1K(const float* __restrict__ w1,
                                              const float* __restrict__ b1,
                                              int l) {
    __shared__ float ws[512];
    int t = threadIdx.x;            // 256
    int f0 = blockIdx.x * 8;
    ws[t]       = w1[f0 * 64 + t];
    ws[t + 256] = w1[f0 * 64 + 256 + t];
    __syncthreads();
    int w = t >> 5, lane = t & 31;
    int f = f0 + w;
    const float* wf = &ws[w * 64];
    float bc_l = 0.f;
    if (l > 0 && lane < 8) bc_l = __ldg(&g_b3cum[(l - 1) * EE + 8 * f + lane]);
    float4 a[8];
    #pragma unroll
    for (int c = 0; c < 8; c++) {
        float bv = __ldg(&b1[f * 8 + c]);
        a[c] = make_float4(bv, bv, bv, bv);
    }
    #pragma unroll
    for (int j = 0; j < 8; j++) {
        int e = 8 * f + j;
        float4 xv = *reinterpret_cast<const float4*>(&g_xe[e * BN + lane * 4]);
        float bc = __shfl_sync(0xffffffffu, bc_l, j);
        xv.x += bc; xv.y += bc; xv.z += bc; xv.w += bc;
        #pragma unroll
        for (int c = 0; c < 8; c++) {
            float wv = wf[j * 8 + c];
            a[c].x += xv.x * wv; a[c].y += xv.y * wv;
            a[c].z += xv.z * wv; a[c].w += xv.w * wv;
        }
    }
    float4 mu = make_float4(0.f, 0.f, 0.f, 0.f);
    #pragma unroll
    for (int c = 0; c < 8; c++) { mu.x += a[c].x; mu.y += a[c].y; mu.z += a[c].z; mu.w += a[c].w; }
    mu.x *= 0.125f; mu.y *= 0.125f; mu.z *= 0.125f; mu.w *= 0.125f;
    float4 var = make_float4(0.f, 0.f, 0.f, 0.f);
    #pragma unroll
    for (int c = 0; c < 8; c++) {
        float dx = a[c].x - mu.x, dy = a[c].y - mu.y, dz = a[c].z - mu.z, dw = a[c].w - mu.w;
        var.x += dx * dx; var.y += dy * dy; var.z += dz * dz; var.w += dw * dw;
    }
    float4 rs;
    rs.x = rsqrtf(var.x * 0.125f + EPSV);
    rs.y = rsqrtf(var.y * 0.125f + EPSV);
    rs.z = rsqrtf(var.z * 0.125f + EPSV);
    rs.w = rsqrtf(var.w * 0.125f + EPSV);
    #pragma unroll
    for (int c = 0; c < 8; c++) {
        int row = f * 8 + c;
        float4 sv = ld_half4(&g_s[row * BN + lane * 4]);
        float4 v;
        v.x = eluf((a[c].x - mu.x) * rs.x * sv.x);
        v.y = eluf((a[c].y - mu.y) * rs.y * sv.y);
        v.z = eluf((a[c].z - mu.z) * rs.z * sv.z);
        v.w = eluf((a[c].w - mu.w) * rs.w * sv.w);
        st_half4(&g_hfc[row * BN + lane * 4], v);
    }
}

// ---------------- spmm3 (warp per fe-edge, fully parallel, float4 xe RMW) ----------------
__global__ void __launch_bounds__(256) spmm3K(const float* __restrict__ w3,
                                              const int* __restrict__ w3rows,
                                              const int* __restrict__ w3cols,
                                              int P) {
    int idx = blockIdx.x * blockDim.x + threadIdx.x;
    int p = idx >> 5, lane = idx & 31;
    if (p >= P) return;
    int fs = __ldg(&w3rows[p * 8]) >> 3;
    int e  = __ldg(&w3cols[p * 8]);
    float4 w0  = *reinterpret_cast<const float4*>(&w3[p * 8]);
    float4 w1v = *reinterpret_cast<const float4*>(&w3[p * 8 + 4]);
    float* xp = &g_xe[(size_t)e * BN + lane * 4];
    float4 acc = *reinterpret_cast<const float4*>(xp);
    const __half* hb = &g_hfc[(size_t)(fs * 8) * BN + lane * 4];
    float4 hv[8];
    #pragma unroll
    for (int c = 0; c < 8; c++) hv[c] = ld_half4(hb + (size_t)c * BN);
    acc.x += hv[0].x * w0.x + hv[1].x * w0.y + hv[2].x * w0.z + hv[3].x * w0.w
           + hv[4].x * w1v.x + hv[5].x * w1v.y + hv[6].x * w1v.z + hv[7].x * w1v.w;
    acc.y += hv[0].y * w0.x + hv[1].y * w0.y + hv[2].y * w0.z + hv[3].y * w0.w
           + hv[4].y * w1v.x + hv[5].y * w1v.y + hv[6].y * w1v.z + hv[7].y * w1v.w;
    acc.z += hv[0].z * w0.x + hv[1].z * w0.y + hv[2].z * w0.z + hv[3].z * w0.w
           + hv[4].z * w1v.x + hv[5].z * w1v.y + hv[6].z * w1v.z + hv[7].z * w1v.w;
    acc.w += hv[0].w * w0.x + hv[1].w * w0.y + hv[2].w * w0.z + hv[3].w * w0.w
           + hv[4].w * w1v.x + hv[5].w * w1v.y + hv[6].w * w1v.z + hv[7].w * w1v.w;
    *reinterpret_cast<float4*>(xp) = acc;
}

// ---------------- final: only out-edges survive the mask ----------------
__global__ void finalK(const int* __restrict__ dst, float* __restrict__ out) {
    int i = blockIdx.x * blockDim.x + threadIdx.x;   // 1000*128
    if (i >= 1000 * BN) return;
    int k = i >> 7, b = i & 127;
    int e = FCC + k;
    float v = (g_xe[(size_t)e * BN + b] + g_b3cum[3 * EE + e]) * 0.25f;
    out[b * NN + dst[e]] = v;
}

// ---------------- launch (single stream) ----------------
extern "C" void kernel_launch(void* const* d_in, const int* in_sizes, int n_in,
                              void* d_out, int out_size) {
    const float* x       = (const float*)d_in[0];
    const float* W_ae1   = (const float*)d_in[1];
    const float* b_ae1   = (const float*)d_in[2];
    const float* W_ae2   = (const float*)d_in[3];
    const float* b_ae2   = (const float*)d_in[4];
    const float* w1_vals = (const float*)d_in[5];
    const float* b1      = (const float*)d_in[6];
    const float* w3_vals = (const float*)d_in[7];
    const float* b3      = (const float*)d_in[8];
    const int*   src     = (const int*)  d_in[9];
    const int*   dst     = (const int*)  d_in[10];
    const int*   w3_rows = (const int*)  d_in[13];
    const int*   w3_cols = (const int*)  d_in[14];
    float* out = (float*)d_out;

    int nnz1 = in_sizes[5] / LL;
    int nnz3 = in_sizes[7] / LL;
    int P = nnz3 / 8;
    int n4 = out_size / 4;
    int prepN = (KPAD * FCC) / 4;
    if (prepN < n4) prepN = n4;
    if (prepN < EE) prepN = EE;

    prepK<<<(prepN + 255) / 256, 256>>>(b3, W_ae2, (float4*)out, n4);
    transposeK<<<dim3(NN / 32, BN / 32), dim3(32, 8)>>>(x);
    gatherK<<<(EE * 32 + 255) / 256, 256>>>(src);

    gemm1K<<<dim3(5, KSPL), 128>>>(W_ae1);
    gemm1finK<<<(BN * HPAD + 255) / 256, 256>>>(b_ae1);
    gemm2K<<<FCC / 64, 256>>>(b_ae2);
    sigK<<<(FCC * 32 + 255) / 256, 256>>>();

    for (int l = 0; l < LL; l++) {
        spmm1K<<<NFN / 8, 256>>>(w1_vals + (size_t)l * nnz1, b1 + (size_t)l * FCC, l);
        spmm3K<<<(P * 32 + 255) / 256, 256>>>(w3_vals + (size_t)l * nnz3, w3_rows, w3_cols, P);
    }

    finalK<<<(1000 * BN) / 256, 256>>>(dst, out);
}

// round 13
// speedup vs baseline: 1.2190x; 1.0289x over previous
#include <cuda_runtime.h>
#include <cuda_fp16.h>
#include <cstdint>

#define BN    128
#define NN    12000
#define NOMIC 3600
#define NFN   7000
#define FCC   56000
#define EE    57000
#define LL    4
#define LAT   100
#define KPAD  112
#define HPAD  120
#define EPSV  1e-5f
#define KSPL  240         // gemm1 k-splits
#define KCH   15          // k per split (240*15=3600)

// ---------------- scratch (device globals; no allocation allowed) ----------------
__device__ float  g_xT[NN * BN];          // x transposed [n][b]
__device__ float  g_xe[EE * BN];          // edge state [e][b] (in-place RMW)
__device__ __half g_zh[FCC * BN];         // z (pre-sigmoid) fp16
__device__ __half g_s [FCC * BN];         // s = sigmoid(LN(z))  fp16
__device__ __half g_hfc[FCC * BN];        // hfc fp16
__device__ __half g_W2h[KPAD * FCC];      // W2 fp16, padded k rows (>=100 are zero)
__device__ __half g_hh[BN * HPAD];        // elu(h) fp16, b-major, padded k (>=100 zero)
__device__ float  g_b3cum[LL * EE];       // cumulative b3 sums
__device__ float  g_hraw[LAT * BN];       // gemm1 accumulator [j][b]
__device__ float  g_red [2 * BN];         // LN sum/sumsq (raw)

// ---------------- helpers ----------------
__device__ __forceinline__ float4 ld_half4(const __half* p) {
    union { uint2 u; __half2 h[2]; } v;
    v.u = *reinterpret_cast<const uint2*>(p);
    float2 a = __half22float2(v.h[0]);
    float2 b = __half22float2(v.h[1]);
    return make_float4(a.x, a.y, b.x, b.y);
}
__device__ __forceinline__ void st_half4(__half* p, float4 v) {
    union { uint2 u; __half2 h[2]; } o;
    o.h[0] = __floats2half2_rn(v.x, v.y);
    o.h[1] = __floats2half2_rn(v.z, v.w);
    *reinterpret_cast<uint2*>(p) = o.u;
}
__device__ __forceinline__ float eluf(float v) { return v > 0.f ? v : expm1f(v); }
__device__ __forceinline__ unsigned packh(__half lo, __half hi) {
    __half2 h = __halves2half2(lo, hi);
    return *reinterpret_cast<unsigned*>(&h);
}

// ---------------- fused prep: zero out/hraw/red + b3cum + W2->fp16 (padded) ----------------
__global__ void prepK(const float* __restrict__ b3, const float* __restrict__ W2,
                      float4* __restrict__ out, int n4) {
    int i = blockIdx.x * blockDim.x + threadIdx.x;
    if (i < n4) out[i] = make_float4(0.f, 0.f, 0.f, 0.f);
    if (i < LAT * BN) g_hraw[i] = 0.f;
    if (i < 2 * BN)   g_red[i] = 0.f;
    if (i < EE) {
        float a = 0.f;
        #pragma unroll
        for (int l = 0; l < LL; l++) { a += b3[l * EE + i]; g_b3cum[l * EE + i] = a; }
    }
    if (i < (KPAD * FCC) / 4) {
        int k = (i * 4) / FCC;
        uint2 o;
        if (k < LAT) {
            float4 w = reinterpret_cast<const float4*>(W2)[i];
            __half2 h0 = __floats2half2_rn(w.x, w.y);
            __half2 h1 = __floats2half2_rn(w.z, w.w);
            o.x = *reinterpret_cast<unsigned*>(&h0);
            o.y = *reinterpret_cast<unsigned*>(&h1);
        } else {
            o.x = 0u; o.y = 0u;
        }
        reinterpret_cast<uint2*>(g_W2h)[i] = o;
    }
}

// ---------------- transpose x : [b][n] -> [n][b] ----------------
__global__ void transposeK(const float* __restrict__ x) {
    __shared__ float t[32][33];
    int n0 = blockIdx.x * 32, b0 = blockIdx.y * 32;
    for (int i = threadIdx.y; i < 32; i += 8)
        t[i][threadIdx.x] = x[(b0 + i) * NN + n0 + threadIdx.x];
    __syncthreads();
    for (int i = threadIdx.y; i < 32; i += 8)
        g_xT[(n0 + i) * BN + b0 + threadIdx.x] = t[threadIdx.x][i];
}

// ---------------- initial edge gather (float4, omic columns zeroed) ----------------
__global__ void gatherK(const int* __restrict__ src) {
    int i = blockIdx.x * blockDim.x + threadIdx.x;   // i = e*32 + lane
    if (i >= EE * 32) return;
    int e = i >> 5, lane = i & 31;
    int s = src[e];
    float4 v = make_float4(0.f, 0.f, 0.f, 0.f);
    if (s >= NOMIC)
        v = *reinterpret_cast<const float4*>(&g_xT[s * BN + lane * 4]);
    *reinterpret_cast<float4*>(&g_xe[e * BN + lane * 4]) = v;
}

// ---------------- gemm1: very fine split-K for occupancy ----------------
__global__ void gemm1K(const float* __restrict__ W1) {
    __shared__ float Wsm[KCH * 20];
    int jt = blockIdx.x, ks = blockIdx.y;   // 5 x KSPL
    int t = threadIdx.x;                    // 128
    for (int idx = t; idx < KCH * 20; idx += 128) {
        int k = idx / 20, j = idx % 20;
        Wsm[idx] = W1[(ks * KCH + k) * LAT + jt * 20 + j];
    }
    __syncthreads();
    float acc[20];
    #pragma unroll
    for (int j = 0; j < 20; j++) acc[j] = 0.f;
    int b = t;
    const float* xp = &g_xT[(ks * KCH) * BN + b];
    float xv[KCH];
    #pragma unroll
    for (int k = 0; k < KCH; k++) xv[k] = xp[k * BN];
    #pragma unroll
    for (int k = 0; k < KCH; k++) {
        #pragma unroll
        for (int j = 0; j < 20; j++) acc[j] += xv[k] * Wsm[k * 20 + j];
    }
    #pragma unroll
    for (int j = 0; j < 20; j++)
        atomicAdd(&g_hraw[(jt * 20 + j) * BN + b], acc[j]);
}

// elu(hraw + bias) -> g_hh [b][HPAD] fp16 (zero-padded k)
__global__ void gemm1finK(const float* __restrict__ b_ae1) {
    int i = blockIdx.x * blockDim.x + threadIdx.x;   // BN*HPAD
    if (i >= BN * HPAD) return;
    int b = i / HPAD, k = i % HPAD;
    float v = 0.f;
    if (k < LAT) v = eluf(g_hraw[k * BN + b] + b_ae1[k]);
    g_hh[i] = __float2half(v);
}

// ---------------- gemm2 via fp16 tensor cores: z = W2^T h + b2 ----------------
__global__ void __launch_bounds__(256) gemm2K(const float* __restrict__ b2) {
    __shared__ __half hh[BN * HPAD];        // 30720 B
    __shared__ float sSum[BN], sSq[BN];
    int t = threadIdx.x;
    {
        const uint4* s = reinterpret_cast<const uint4*>(g_hh);
        uint4* d = reinterpret_cast<uint4*>(hh);
        #pragma unroll
        for (int i = 0; i < 8; i++) {
            int idx = t + i * 256;
            if (idx < (BN * HPAD) / 8) d[idx] = s[idx];
        }
    }
    if (t < BN) { sSum[t] = 0.f; sSq[t] = 0.f; }
    __syncthreads();

    int w = t >> 5, lane = t & 31;
    int g = lane >> 2, tg = lane & 3;
    int jsub = w & 3, bhalf = w >> 2;
    int j0 = blockIdx.x * 64 + jsub * 16;
    int jr0 = j0 + g, jr1 = j0 + g + 8;

    float c[8][4];
    #pragma unroll
    for (int nt = 0; nt < 8; nt++)
        c[nt][0] = c[nt][1] = c[nt][2] = c[nt][3] = 0.f;

    #pragma unroll
    for (int ks = 0; ks < 7; ks++) {
        int k = ks * 16 + 2 * tg;
        unsigned a0 = packh(g_W2h[(size_t)k * FCC + jr0],       g_W2h[(size_t)(k + 1) * FCC + jr0]);
        unsigned a1 = packh(g_W2h[(size_t)k * FCC + jr1],       g_W2h[(size_t)(k + 1) * FCC + jr1]);
        unsigned a2 = packh(g_W2h[(size_t)(k + 8) * FCC + jr0], g_W2h[(size_t)(k + 9) * FCC + jr0]);
        unsigned a3 = packh(g_W2h[(size_t)(k + 8) * FCC + jr1], g_W2h[(size_t)(k + 9) * FCC + jr1]);
        #pragma unroll
        for (int nt = 0; nt < 8; nt++) {
            int nb = bhalf * 64 + nt * 8 + g;
            unsigned b0 = *reinterpret_cast<const unsigned*>(&hh[nb * HPAD + k]);
            unsigned b1 = *reinterpret_cast<const unsigned*>(&hh[nb * HPAD + k + 8]);
            asm volatile(
                "mma.sync.aligned.m16n8k16.row.col.f32.f16.f16.f32 "
                "{%0,%1,%2,%3}, {%4,%5,%6,%7}, {%8,%9}, {%0,%1,%2,%3};"
                : "+f"(c[nt][0]), "+f"(c[nt][1]), "+f"(c[nt][2]), "+f"(c[nt][3])
                : "r"(a0), "r"(a1), "r"(a2), "r"(a3), "r"(b0), "r"(b1));
        }
    }

    float bias0 = b2[jr0], bias1 = b2[jr1];
    #pragma unroll
    for (int nt = 0; nt < 8; nt++) {
        int bc = bhalf * 64 + nt * 8 + 2 * tg;
        float v0 = c[nt][0] + bias0, v1 = c[nt][1] + bias0;
        float v2 = c[nt][2] + bias1, v3 = c[nt][3] + bias1;
        *reinterpret_cast<__half2*>(&g_zh[(size_t)jr0 * BN + bc]) = __floats2half2_rn(v0, v1);
        *reinterpret_cast<__half2*>(&g_zh[(size_t)jr1 * BN + bc]) = __floats2half2_rn(v2, v3);
        atomicAdd(&sSum[bc],     v0 + v2);
        atomicAdd(&sSq[bc],      v0 * v0 + v2 * v2);
        atomicAdd(&sSum[bc + 1], v1 + v3);
        atomicAdd(&sSq[bc + 1],  v1 * v1 + v3 * v3);
    }
    __syncthreads();
    if (t < BN) {
        atomicAdd(&g_red[t], sSum[t]);
        atomicAdd(&g_red[BN + t], sSq[t]);
    }
}

// sigmoid(LN(z)) -> fp16 s; LN stats inline from raw sums
__global__ void sigK() {
    int i = blockIdx.x * blockDim.x + threadIdx.x;
    if (i >= FCC * 32) return;
    int lane = i & 31;
    const float inv = 1.f / (float)FCC;
    float4 z  = ld_half4(&g_zh[i * 4]);
    float4 sm = *reinterpret_cast<const float4*>(&g_red[lane * 4]);
    float4 sq = *reinterpret_cast<const float4*>(&g_red[BN + lane * 4]);
    float4 mu, rs;
    mu.x = sm.x * inv; mu.y = sm.y * inv; mu.z = sm.z * inv; mu.w = sm.w * inv;
    rs.x = rsqrtf(sq.x * inv - mu.x * mu.x + EPSV);
    rs.y = rsqrtf(sq.y * inv - mu.y * mu.y + EPSV);
    rs.z = rsqrtf(sq.z * inv - mu.z * mu.z + EPSV);
    rs.w = rsqrtf(sq.w * inv - mu.w * mu.w + EPSV);
    float4 v;
    v.x = 1.f / (1.f + __expf(-(z.x - mu.x) * rs.x));
    v.y = 1.f / (1.f + __expf(-(z.y - mu.y) * rs.y));
    v.z = 1.f / (1.f + __expf(-(z.z - mu.z) * rs.z));
    v.w = 1.f / (1.f + __expf(-(z.w - mu.w) * rs.w));
    st_half4(&g_s[i * 4], v);
}

// ---------------- spmm1 + groupLN + s*elu (warp per function, float4 over b) ----------------
__global__ void __launch_bounds__(256) spmm1K(const float* __restrict__ w1,
                                              const float* __restrict__ b1,
                                              int l) {
    __shared__ float ws[512];
    int t = threadIdx.x;            // 256
    int f0 = blockIdx.x * 8;
    ws[t]       = w1[f0 * 64 + t];
    ws[t + 256] = w1[f0 * 64 + 256 + t];
    __syncthreads();
    int w = t >> 5, lane = t & 31;
    int f = f0 + w;
    const float* wf = &ws[w * 64];
    float bc_l = 0.f;
    if (l > 0 && lane < 8) bc_l = __ldg(&g_b3cum[(l - 1) * EE + 8 * f + lane]);
    float4 a[8];
    #pragma unroll
    for (int c = 0; c < 8; c++) {
        float bv = __ldg(&b1[f * 8 + c]);
        a[c] = make_float4(bv, bv, bv, bv);
    }
    #pragma unroll
    for (int j = 0; j < 8; j++) {
        int e = 8 * f + j;
        float4 xv = *reinterpret_cast<const float4*>(&g_xe[e * BN + lane * 4]);
        float bc = __shfl_sync(0xffffffffu, bc_l, j);
        xv.x += bc; xv.y += bc; xv.z += bc; xv.w += bc;
        #pragma unroll
        for (int c = 0; c < 8; c++) {
            float wv = wf[j * 8 + c];
            a[c].x += xv.x * wv; a[c].y += xv.y * wv;
            a[c].z += xv.z * wv; a[c].w += xv.w * wv;
        }
    }
    float4 mu = make_float4(0.f, 0.f, 0.f, 0.f);
    #pragma unroll
    for (int c = 0; c < 8; c++) { mu.x += a[c].x; mu.y += a[c].y; mu.z += a[c].z; mu.w += a[c].w; }
    mu.x *= 0.125f; mu.y *= 0.125f; mu.z *= 0.125f; mu.w *= 0.125f;
    float4 var = make_float4(0.f, 0.f, 0.f, 0.f);
    #pragma unroll
    for (int c = 0; c < 8; c++) {
        float dx = a[c].x - mu.x, dy = a[c].y - mu.y, dz = a[c].z - mu.z, dw = a[c].w - mu.w;
        var.x += dx * dx; var.y += dy * dy; var.z += dz * dz; var.w += dw * dw;
    }
    float4 rs;
    rs.x = rsqrtf(var.x * 0.125f + EPSV);
    rs.y = rsqrtf(var.y * 0.125f + EPSV);
    rs.z = rsqrtf(var.z * 0.125f + EPSV);
    rs.w = rsqrtf(var.w * 0.125f + EPSV);
    #pragma unroll
    for (int c = 0; c < 8; c++) {
        int row = f * 8 + c;
        float4 sv = ld_half4(&g_s[row * BN + lane * 4]);
        float4 v;
        v.x = eluf((a[c].x - mu.x) * rs.x * sv.x);
        v.y = eluf((a[c].y - mu.y) * rs.y * sv.y);
        v.z = eluf((a[c].z - mu.z) * rs.z * sv.z);
        v.w = eluf((a[c].w - mu.w) * rs.w * sv.w);
        st_half4(&g_hfc[row * BN + lane * 4], v);
    }
}

// ---------------- spmm3 (warp per fe-edge, fully parallel, float4 xe RMW) ----------------
__global__ void __launch_bounds__(256) spmm3K(const float* __restrict__ w3,
                                              const int* __restrict__ w3rows,
                                              const int* __restrict__ w3cols,
                                              int P) {
    int idx = blockIdx.x * blockDim.x + threadIdx.x;
    int p = idx >> 5, lane = idx & 31;
    if (p >= P) return;
    int fs = __ldg(&w3rows[p * 8]) >> 3;
    int e  = __ldg(&w3cols[p * 8]);
    float4 w0  = *reinterpret_cast<const float4*>(&w3[p * 8]);
    float4 w1v = *reinterpret_cast<const float4*>(&w3[p * 8 + 4]);
    float* xp = &g_xe[(size_t)e * BN + lane * 4];
    float4 acc = *reinterpret_cast<const float4*>(xp);
    const __half* hb = &g_hfc[(size_t)(fs * 8) * BN + lane * 4];
    float4 hv[8];
    #pragma unroll
    for (int c = 0; c < 8; c++) hv[c] = ld_half4(hb + (size_t)c * BN);
    acc.x += hv[0].x * w0.x + hv[1].x * w0.y + hv[2].x * w0.z + hv[3].x * w0.w
           + hv[4].x * w1v.x + hv[5].x * w1v.y + hv[6].x * w1v.z + hv[7].x * w1v.w;
    acc.y += hv[0].y * w0.x + hv[1].y * w0.y + hv[2].y * w0.z + hv[3].y * w0.w
           + hv[4].y * w1v.x + hv[5].y * w1v.y + hv[6].y * w1v.z + hv[7].y * w1v.w;
    acc.z += hv[0].z * w0.x + hv[1].z * w0.y + hv[2].z * w0.z + hv[3].z * w0.w
           + hv[4].z * w1v.x + hv[5].z * w1v.y + hv[6].z * w1v.z + hv[7].z * w1v.w;
    acc.w += hv[0].w * w0.x + hv[1].w * w0.y + hv[2].w * w0.z + hv[3].w * w0.w
           + hv[4].w * w1v.x + hv[5].w * w1v.y + hv[6].w * w1v.z + hv[7].w * w1v.w;
    *reinterpret_cast<float4*>(xp) = acc;
}

// ---------------- final: only out-edges survive the mask ----------------
__global__ void finalK(const int* __restrict__ dst, float* __restrict__ out) {
    int i = blockIdx.x * blockDim.x + threadIdx.x;   // 1000*128
    if (i >= 1000 * BN) return;
    int k = i >> 7, b = i & 127;
    int e = FCC + k;
    float v = (g_xe[(size_t)e * BN + b] + g_b3cum[3 * EE + e]) * 0.25f;
    out[b * NN + dst[e]] = v;
}

// ---------------- launch (single stream) ----------------
extern "C" void kernel_launch(void* const* d_in, const int* in_sizes, int n_in,
                              void* d_out, int out_size) {
    const float* x       = (const float*)d_in[0];
    const float* W_ae1   = (const float*)d_in[1];
    const float* b_ae1   = (const float*)d_in[2];
    const float* W_ae2   = (const float*)d_in[3];
    const float* b_ae2   = (const float*)d_in[4];
    const float* w1_vals = (const float*)d_in[5];
    const float* b1      = (const float*)d_in[6];
    const float* w3_vals = (const float*)d_in[7];
    const float* b3      = (const float*)d_in[8];
    const int*   src     = (const int*)  d_in[9];
    const int*   dst     = (const int*)  d_in[10];
    const int*   w3_rows = (const int*)  d_in[13];
    const int*   w3_cols = (const int*)  d_in[14];
    float* out = (float*)d_out;

    int nnz1 = in_sizes[5] / LL;
    int nnz3 = in_sizes[7] / LL;
    int P = nnz3 / 8;
    int n4 = out_size / 4;
    int prepN = (KPAD * FCC) / 4;
    if (prepN < n4) prepN = n4;
    if (prepN < EE) prepN = EE;

    prepK<<<(prepN + 255) / 256, 256>>>(b3, W_ae2, (float4*)out, n4);
    transposeK<<<dim3(NN / 32, BN / 32), dim3(32, 8)>>>(x);
    gatherK<<<(EE * 32 + 255) / 256, 256>>>(src);

    gemm1K<<<dim3(5, KSPL), 128>>>(W_ae1);
    gemm1finK<<<(BN * HPAD + 255) / 256, 256>>>(b_ae1);
    gemm2K<<<FCC / 64, 256>>>(b_ae2);
    sigK<<<(FCC * 32 + 255) / 256, 256>>>();

    for (int l = 0; l < LL; l++) {
        spmm1K<<<NFN / 8, 256>>>(w1_vals + (size_t)l * nnz1, b1 + (size_t)l * FCC, l);
        spmm3K<<<(P * 32 + 255) / 256, 256>>>(w3_vals + (size_t)l * nnz3, w3_rows, w3_cols, P);
    }

    finalK<<<(1000 * BN) / 256, 256>>>(dst, out);
}